// round 3
// baseline (speedup 1.0000x reference)
#include <cuda_runtime.h>

#define NP 262144
#define GRIDW 256
#define NUM_CELLS (GRIDW*GRIDW)
#define KSLOT 32
#define CAP 64
#define MAXN 64
#define FULLM 0xffffffffu

// ---------------- scratch (device globals) ----------------------------------
__device__ unsigned g_maxH;
__device__ unsigned g_minX;
__device__ unsigned g_minY;
__device__ unsigned g_qtotal;
__device__ int      g_cellCount[NUM_CELLS + 1];
__device__ float4   g_cellListP[NUM_CELLS * CAP];       // {bits(idx), x, y, pad}
__device__ int      g_tabCnt[NUM_CELLS + 1];
__device__ float4   g_tab[(NUM_CELLS + 1) * KSLOT];     // {bits(idx), x, y, pad}
__device__ float4   g_qorder[NP];                       // {bits(qid), x, y, bits(cell)}

// ---------------- kernel 0: reset -------------------------------------------
__global__ void initK() {
    int i = blockIdx.x * blockDim.x + threadIdx.x;
    if (i == 0) {
        g_maxH = 0u;
        g_minX = 0x7f800000u;   // +inf (coords >= 0 -> uint order == float order)
        g_minY = 0x7f800000u;
        g_qtotal = 0u;
        g_tabCnt[NUM_CELLS] = 0;  // sentinel cell is always empty
    }
    for (int c = i; c <= NUM_CELLS; c += gridDim.x * blockDim.x)
        g_cellCount[c] = 0;
}

// ---------------- kernel 1: reductions --------------------------------------
__global__ void reduceK(const float* __restrict__ pos, const float* __restrict__ sup) {
    __shared__ float sH[256], sX[256], sY[256];
    float h = 0.0f, x = __int_as_float(0x7f800000), y = __int_as_float(0x7f800000);
    for (int i = blockIdx.x * blockDim.x + threadIdx.x; i < NP;
         i += gridDim.x * blockDim.x) {
        h = fmaxf(h, sup[i]);
        float2 p = ((const float2*)pos)[i];
        x = fminf(x, p.x);
        y = fminf(y, p.y);
    }
    int t = threadIdx.x;
    sH[t] = h; sX[t] = x; sY[t] = y;
    __syncthreads();
    for (int s = blockDim.x / 2; s > 0; s >>= 1) {
        if (t < s) {
            sH[t] = fmaxf(sH[t], sH[t + s]);
            sX[t] = fminf(sX[t], sX[t + s]);
            sY[t] = fminf(sY[t], sY[t + s]);
        }
        __syncthreads();
    }
    if (t == 0) {
        atomicMax(&g_maxH, __float_as_uint(sH[0]));
        atomicMin(&g_minX, __float_as_uint(sX[0]));
        atomicMin(&g_minY, __float_as_uint(sY[0]));
    }
}

// ---------------- kernel 2: bin particles (pos fused into list) -------------
__global__ void binK(const float* __restrict__ pos) {
    int i = blockIdx.x * blockDim.x + threadIdx.x;
    if (i >= NP) return;
    float h  = __uint_as_float(g_maxH);
    float qx = __uint_as_float(g_minX) - h;
    float qy = __uint_as_float(g_minY) - h;
    float2 p = ((const float2*)pos)[i];
    int ix = (int)ceilf((p.x - qx) / h);
    int iy = (int)ceilf((p.y - qy) / h);
    ix = min(max(ix, 0), GRIDW - 1);
    iy = min(max(iy, 0), GRIDW - 1);
    int lin = ix + GRIDW * iy;
    int slot = atomicAdd(&g_cellCount[lin], 1);
    if (slot < CAP)
        g_cellListP[lin * CAP + slot] = make_float4(__int_as_float(i), p.x, p.y, 0.0f);
}

// ---------------- kernel 3: warp-per-cell rank sort (gather-free) -----------
__global__ void sortK() {
    int w = (blockIdx.x * blockDim.x + threadIdx.x) >> 5;
    if (w >= NUM_CELLS) return;
    int lane = threadIdx.x & 31;
    int cnt = g_cellCount[w];
    int m = min(cnt, KSLOT);
    float4 e = make_float4(0.f, 0.f, 0.f, 0.f);
    int idx = 0x7fffffff;
    if (lane < m) {
        e = g_cellListP[w * CAP + lane];
        idx = __float_as_int(e.x);
    }
    int rank = 0;
    for (int j = 0; j < m; j++) {
        int v = __shfl_sync(FULLM, idx, j);
        rank += (v < idx);
    }
    if (lane == 0) g_tabCnt[w] = m;
    if (lane < m) g_tab[w * KSLOT + rank] = e;
}

// ---------------- kernel 3b: build cell-ordered query list ------------------
__global__ void compactK() {
    int c = blockIdx.x * blockDim.x + threadIdx.x;   // 256 blocks x 256 thr
    int cnt = min(g_cellCount[c], CAP);
    int lane = threadIdx.x & 31, wid = threadIdx.x >> 5;
    int incl = cnt;
#pragma unroll
    for (int d = 1; d < 32; d <<= 1) {
        int t = __shfl_up_sync(FULLM, incl, d);
        if (lane >= d) incl += t;
    }
    __shared__ int wtot[8];
    __shared__ int blockBase;
    if (lane == 31) wtot[wid] = incl;
    __syncthreads();
    if (threadIdx.x == 0) {
        int tot = 0;
        for (int w = 0; w < 8; w++) { int t = wtot[w]; wtot[w] = tot; tot += t; }
        blockBase = (int)atomicAdd(&g_qtotal, (unsigned)tot);
    }
    __syncthreads();
    int off = blockBase + wtot[wid] + incl - cnt;
    for (int s = 0; s < cnt; s++) {
        float4 e = g_cellListP[c * CAP + s];
        g_qorder[off + s] = make_float4(e.x, e.y, e.z, __int_as_float(c));
    }
}

// ---------------- kernel 4: warp-per-query neighbor search ------------------
__global__ void searchK(const float* __restrict__ sup,
                        float* __restrict__ out) {
    int gw = (blockIdx.x * blockDim.x + threadIdx.x) >> 5;
    if (gw >= NP) return;
    int lane = threadIdx.x & 31;

    float4 q = g_qorder[gw];
    int   qid = __float_as_int(q.x);
    float px  = q.y, py = q.z;
    int   lin = __float_as_int(q.w);
    float h   = __ldg(&sup[qid]);

    // lanes 0..8 own the 9 stencil cells (reference offs order)
    int c = NUM_CELLS, m = 0;
    if (lane < 9) {
        int dxo = lane / 3 - 1;
        int dyo = lane % 3 - 1;
        int cc = lin + dxo + GRIDW * dyo;
        cc = min(max(cc, 0), NUM_CELLS);
        c = cc;
        m = g_tabCnt[cc];
    }
    int incl = m;
#pragma unroll
    for (int d = 1; d < 32; d <<= 1) {
        int v = __shfl_up_sync(FULLM, incl, d);
        if (lane >= d) incl += v;
    }
    int pref = incl - m;
    int T = __shfl_sync(FULLM, incl, 8);

    int p1 = __shfl_sync(FULLM, pref, 1);
    int p2 = __shfl_sync(FULLM, pref, 2);
    int p3 = __shfl_sync(FULLM, pref, 3);
    int p4 = __shfl_sync(FULLM, pref, 4);
    int p5 = __shfl_sync(FULLM, pref, 5);
    int p6 = __shfl_sync(FULLM, pref, 6);
    int p7 = __shfl_sync(FULLM, pref, 7);
    int p8 = __shfl_sync(FULLM, pref, 8);

    float* outN = out;                              // (N, 64) neighbor indices
    float* outC = out + (size_t)NP * MAXN;          // (N,)    counts
    float* outR = outC + NP;                        // (N, 64) radial
    size_t base = (size_t)qid * MAXN;

    int cnt = 0;
    for (int tb = 0; tb < T; tb += 32) {
        int t = tb + lane;
        bool act = t < T;
        int o = (t >= p1) + (t >= p2) + (t >= p3) + (t >= p4) +
                (t >= p5) + (t >= p6) + (t >= p7) + (t >= p8);
        int cc = __shfl_sync(FULLM, c, o);
        int po = __shfl_sync(FULLM, pref, o);
        int s  = t - po;

        float nidx = 0.0f, dist = 0.0f;
        bool ok = false;
        if (act) {
            float4 e = g_tab[cc * KSLOT + s];
            float dx = __fsub_rn(e.y, px);
            float dy = __fsub_rn(e.z, py);
            float d2 = __fadd_rn(__fmul_rn(dx, dx), __fmul_rn(dy, dy));
            dist = __fsqrt_rn(d2);
            nidx = (float)__float_as_int(e.x);
            ok = (dist <= h);
        }
        unsigned bal = __ballot_sync(FULLM, ok);
        int slot = cnt + __popc(bal & ((1u << lane) - 1u));
        if (ok && slot < MAXN) {
            __stcs(&outN[base + slot], nidx);
            __stcs(&outR[base + slot], __fdiv_rn(dist, h));
        }
        cnt += __popc(bal);
    }
    int start = min(cnt, MAXN);
    for (int k = start + lane; k < MAXN; k += 32) {
        __stcs(&outN[base + k], -1.0f);
        __stcs(&outR[base + k], 0.0f);
    }
    if (lane == 0) __stcs(&outC[qid], (float)cnt);
}

// ---------------- launch ------------------------------------------------------
extern "C" void kernel_launch(void* const* d_in, const int* in_sizes, int n_in,
                              void* d_out, int out_size) {
    const float* pos = (const float*)d_in[0];   // (N, 2) float32
    const float* sup = (const float*)d_in[1];   // (N,)   float32
    float* out = (float*)d_out;

    initK<<<256, 256>>>();
    reduceK<<<256, 256>>>(pos, sup);
    binK<<<NP / 256, 256>>>(pos);
    sortK<<<(NUM_CELLS * 32) / 256, 256>>>();
    compactK<<<NUM_CELLS / 256, 256>>>();
    searchK<<<(NP * 32) / 256, 256>>>(sup, out);
}

// round 4
// speedup vs baseline: 1.0668x; 1.0668x over previous
#include <cuda_runtime.h>

#define NP 262144
#define GRIDW 256
#define NUM_CELLS (GRIDW*GRIDW)
#define KSLOT 32
#define CAP 32
#define MAXN 64
#define FULLM 0xffffffffu

// ---------------- scratch (device globals) ----------------------------------
__device__ unsigned g_maxH;
__device__ unsigned g_minX;
__device__ unsigned g_minY;
__device__ int      g_cellCount[NUM_CELLS + 1];
__device__ float4   g_cellListP[NUM_CELLS * CAP];       // {bits(idx), x, y, pad}
__device__ int      g_tabCnt[NUM_CELLS + 1];
__device__ float4   g_tab[(NUM_CELLS + 1) * KSLOT];     // {bits(idx), x, y, pad}

// ---------------- kernel 0: reset -------------------------------------------
__global__ void initK() {
    int i = blockIdx.x * blockDim.x + threadIdx.x;
    if (i == 0) {
        g_maxH = 0u;
        g_minX = 0x7f800000u;   // +inf (coords >= 0 -> uint order == float order)
        g_minY = 0x7f800000u;
        g_tabCnt[NUM_CELLS] = 0;  // sentinel cell: always empty
    }
    for (int c = i; c <= NUM_CELLS; c += gridDim.x * blockDim.x)
        g_cellCount[c] = 0;
}

// ---------------- kernel 1: reductions --------------------------------------
__global__ void reduceK(const float* __restrict__ pos, const float* __restrict__ sup) {
    __shared__ float sH[256], sX[256], sY[256];
    float h = 0.0f, x = __int_as_float(0x7f800000), y = __int_as_float(0x7f800000);
    for (int i = blockIdx.x * blockDim.x + threadIdx.x; i < NP;
         i += gridDim.x * blockDim.x) {
        h = fmaxf(h, sup[i]);
        float2 p = ((const float2*)pos)[i];
        x = fminf(x, p.x);
        y = fminf(y, p.y);
    }
    int t = threadIdx.x;
    sH[t] = h; sX[t] = x; sY[t] = y;
    __syncthreads();
    for (int s = blockDim.x / 2; s > 0; s >>= 1) {
        if (t < s) {
            sH[t] = fmaxf(sH[t], sH[t + s]);
            sX[t] = fminf(sX[t], sX[t + s]);
            sY[t] = fminf(sY[t], sY[t + s]);
        }
        __syncthreads();
    }
    if (t == 0) {
        atomicMax(&g_maxH, __float_as_uint(sH[0]));
        atomicMin(&g_minX, __float_as_uint(sX[0]));
        atomicMin(&g_minY, __float_as_uint(sY[0]));
    }
}

// ---------------- kernel 2: bin particles (pos fused into list) -------------
__global__ void binK(const float* __restrict__ pos) {
    int i = blockIdx.x * blockDim.x + threadIdx.x;
    if (i >= NP) return;
    float h  = __uint_as_float(g_maxH);
    float qx = __uint_as_float(g_minX) - h;
    float qy = __uint_as_float(g_minY) - h;
    float2 p = ((const float2*)pos)[i];
    int ix = (int)ceilf((p.x - qx) / h);
    int iy = (int)ceilf((p.y - qy) / h);
    ix = min(max(ix, 0), GRIDW - 1);
    iy = min(max(iy, 0), GRIDW - 1);
    int lin = ix + GRIDW * iy;
    int slot = atomicAdd(&g_cellCount[lin], 1);
    if (slot < CAP)
        g_cellListP[lin * CAP + slot] = make_float4(__int_as_float(i), p.x, p.y, 0.0f);
}

// ---------------- kernel 3: warp-per-cell rank sort (gather-free) -----------
__global__ void sortK() {
    int w = (blockIdx.x * blockDim.x + threadIdx.x) >> 5;
    if (w >= NUM_CELLS) return;
    int lane = threadIdx.x & 31;
    int cnt = g_cellCount[w];
    int m = min(cnt, KSLOT);
    float4 e = make_float4(0.f, 0.f, 0.f, 0.f);
    int idx = 0x7fffffff;
    if (lane < m) {
        e = g_cellListP[w * CAP + lane];
        idx = __float_as_int(e.x);
    }
    int rank = 0;
    for (int j = 0; j < m; j++) {
        int v = __shfl_sync(FULLM, idx, j);
        rank += (v < idx);
    }
    if (lane == 0) g_tabCnt[w] = m;
    if (lane < m) g_tab[w * KSLOT + rank] = e;
}

// ---------------- kernel 4: warp-per-CELL neighbor search -------------------
__global__ void searchK(const float* __restrict__ sup,
                        float* __restrict__ out) {
    int w = (blockIdx.x * blockDim.x + threadIdx.x) >> 5;   // warp id = cell
    if (w >= NUM_CELLS) return;
    int lane = threadIdx.x & 31;

    int qcnt = min(g_cellCount[w], CAP);
    if (qcnt == 0) return;

    // ---- stencil setup (once per cell) ----
    int c = NUM_CELLS, m = 0;
    if (lane < 9) {
        int dxo = lane / 3 - 1;
        int dyo = lane % 3 - 1;
        int cc = w + dxo + GRIDW * dyo;
        cc = min(max(cc, 0), NUM_CELLS);
        c = cc;
        m = g_tabCnt[cc];
    }
    int incl = m;
#pragma unroll
    for (int d = 1; d < 16; d <<= 1) {
        int v = __shfl_up_sync(FULLM, incl, d);
        if (lane >= d) incl += v;
    }
    int pref = incl - m;
    int T = __shfl_sync(FULLM, incl, 8);

    int p1 = __shfl_sync(FULLM, pref, 1);
    int p2 = __shfl_sync(FULLM, pref, 2);
    int p3 = __shfl_sync(FULLM, pref, 3);
    int p4 = __shfl_sync(FULLM, pref, 4);
    int p5 = __shfl_sync(FULLM, pref, 5);
    int p6 = __shfl_sync(FULLM, pref, 6);
    int p7 = __shfl_sync(FULLM, pref, 7);
    int p8 = __shfl_sync(FULLM, pref, 8);

    // ---- preload candidates (chunks 0 and 1 cover T <= 64) ----
    float4 e0 = make_float4(0.f, 0.f, 0.f, 0.f);
    float4 e1 = make_float4(0.f, 0.f, 0.f, 0.f);
    bool act0 = lane < T;
    {
        int t = lane;
        int o = (t >= p1) + (t >= p2) + (t >= p3) + (t >= p4) +
                (t >= p5) + (t >= p6) + (t >= p7) + (t >= p8);
        int cc = __shfl_sync(FULLM, c, o);
        int po = __shfl_sync(FULLM, pref, o);
        if (act0) e0 = g_tab[cc * KSLOT + (t - po)];
    }
    bool act1 = (lane + 32) < T;
    if (T > 32) {
        int t = lane + 32;
        int o = (t >= p1) + (t >= p2) + (t >= p3) + (t >= p4) +
                (t >= p5) + (t >= p6) + (t >= p7) + (t >= p8);
        int cc = __shfl_sync(FULLM, c, o);
        int po = __shfl_sync(FULLM, pref, o);
        if (act1) e1 = g_tab[cc * KSLOT + (t - po)];
    }
    float n0 = (float)__float_as_int(e0.x);
    float n1 = (float)__float_as_int(e1.x);

    // ---- query data (this cell's own particles) ----
    float4 qe = make_float4(0.f, 0.f, 0.f, 0.f);
    float hq = 0.0f;
    int qidl = 0;
    if (lane < qcnt) {
        qe = g_cellListP[w * CAP + lane];
        qidl = __float_as_int(qe.x);
        hq = __ldg(&sup[qidl]);
    }

    float* outN = out;                              // (N, 64) neighbor indices
    float* outC = out + (size_t)NP * MAXN;          // (N,)    counts
    float* outR = outC + NP;                        // (N, 64) radial

    // ---- per-query loop ----
    for (int q = 0; q < qcnt; q++) {
        float px = __shfl_sync(FULLM, qe.y, q);
        float py = __shfl_sync(FULLM, qe.z, q);
        float h  = __shfl_sync(FULLM, hq, q);
        int  qid = __shfl_sync(FULLM, qidl, q);
        size_t base = (size_t)qid * MAXN;

        int cnt = 0;
        // chunk 0
        {
            float dx = __fsub_rn(e0.y, px);
            float dy = __fsub_rn(e0.z, py);
            float dist = __fsqrt_rn(__fadd_rn(__fmul_rn(dx, dx), __fmul_rn(dy, dy)));
            bool ok = act0 && (dist <= h);
            unsigned bal = __ballot_sync(FULLM, ok);
            int slot = __popc(bal & ((1u << lane) - 1u));
            if (ok && slot < MAXN) {
                outN[base + slot] = n0;
                outR[base + slot] = __fdiv_rn(dist, h);
            }
            cnt = __popc(bal);
        }
        // chunk 1
        if (T > 32) {
            float dx = __fsub_rn(e1.y, px);
            float dy = __fsub_rn(e1.z, py);
            float dist = __fsqrt_rn(__fadd_rn(__fmul_rn(dx, dx), __fmul_rn(dy, dy)));
            bool ok = act1 && (dist <= h);
            unsigned bal = __ballot_sync(FULLM, ok);
            int slot = cnt + __popc(bal & ((1u << lane) - 1u));
            if (ok && slot < MAXN) {
                outN[base + slot] = n1;
                outR[base + slot] = __fdiv_rn(dist, h);
            }
            cnt += __popc(bal);
        }
        // rare: T > 64
        for (int tb = 64; tb < T; tb += 32) {
            int t = tb + lane;
            bool act = t < T;
            int o = (t >= p1) + (t >= p2) + (t >= p3) + (t >= p4) +
                    (t >= p5) + (t >= p6) + (t >= p7) + (t >= p8);
            int cc = __shfl_sync(FULLM, c, o);
            int po = __shfl_sync(FULLM, pref, o);
            float nidx = 0.0f, dist = 0.0f;
            bool ok = false;
            if (act) {
                float4 e = g_tab[cc * KSLOT + (t - po)];
                float dx = __fsub_rn(e.y, px);
                float dy = __fsub_rn(e.z, py);
                dist = __fsqrt_rn(__fadd_rn(__fmul_rn(dx, dx), __fmul_rn(dy, dy)));
                nidx = (float)__float_as_int(e.x);
                ok = dist <= h;
            }
            unsigned bal = __ballot_sync(FULLM, ok);
            int slot = cnt + __popc(bal & ((1u << lane) - 1u));
            if (ok && slot < MAXN) {
                outN[base + slot] = nidx;
                outR[base + slot] = __fdiv_rn(dist, h);
            }
            cnt += __popc(bal);
        }
        // tail fill
        int start = min(cnt, MAXN);
        for (int k = start + lane; k < MAXN; k += 32) {
            outN[base + k] = -1.0f;
            outR[base + k] = 0.0f;
        }
        if (lane == 0) outC[qid] = (float)cnt;
    }
}

// ---------------- launch ------------------------------------------------------
extern "C" void kernel_launch(void* const* d_in, const int* in_sizes, int n_in,
                              void* d_out, int out_size) {
    const float* pos = (const float*)d_in[0];   // (N, 2) float32
    const float* sup = (const float*)d_in[1];   // (N,)   float32
    float* out = (float*)d_out;

    initK<<<256, 256>>>();
    reduceK<<<256, 256>>>(pos, sup);
    binK<<<NP / 256, 256>>>(pos);
    sortK<<<(NUM_CELLS * 32) / 256, 256>>>();
    searchK<<<(NUM_CELLS * 32) / 256, 256>>>(sup, out);
}

// round 6
// speedup vs baseline: 1.1721x; 1.0987x over previous
#include <cuda_runtime.h>

#define NP 262144
#define GRIDW 256
#define NUM_CELLS (GRIDW*GRIDW)
#define KSLOT 32
#define CAP 32
#define MAXN 64
#define FULLM 0xffffffffu

// ---------------- scratch (device globals) ----------------------------------
__device__ float    g_partH[256];
__device__ float    g_partX[256];
__device__ float    g_partY[256];
__device__ int      g_cellCount[NUM_CELLS + 1];
__device__ float4   g_cellListP[NUM_CELLS * CAP];       // {bits(idx), x, y, pad}
__device__ int      g_tabCnt[NUM_CELLS + 1];
__device__ float4   g_tab[(NUM_CELLS + 1) * KSLOT];     // {bits(idx), x, y, pad}

// ------- kernel 1: zero counts + per-block partial reductions ---------------
__global__ void initRedK(const float* __restrict__ pos, const float* __restrict__ sup) {
    int tid = blockIdx.x * blockDim.x + threadIdx.x;
    for (int c = tid; c <= NUM_CELLS; c += gridDim.x * blockDim.x)
        g_cellCount[c] = 0;
    if (tid == 0) g_tabCnt[NUM_CELLS] = 0;   // sentinel cell: always empty

    __shared__ float sH[256], sX[256], sY[256];
    float h = 0.0f, x = __int_as_float(0x7f800000), y = __int_as_float(0x7f800000);
    for (int i = tid; i < NP; i += gridDim.x * blockDim.x) {
        h = fmaxf(h, sup[i]);
        float2 p = ((const float2*)pos)[i];
        x = fminf(x, p.x);
        y = fminf(y, p.y);
    }
    int t = threadIdx.x;
    sH[t] = h; sX[t] = x; sY[t] = y;
    __syncthreads();
    for (int s = 128; s > 0; s >>= 1) {
        if (t < s) {
            sH[t] = fmaxf(sH[t], sH[t + s]);
            sX[t] = fminf(sX[t], sX[t + s]);
            sY[t] = fminf(sY[t], sY[t + s]);
        }
        __syncthreads();
    }
    if (t == 0) {
        g_partH[blockIdx.x] = sH[0];
        g_partX[blockIdx.x] = sX[0];
        g_partY[blockIdx.x] = sY[0];
    }
}

// ------- kernel 2: combine partials (prologue) + bin particles --------------
__global__ void binK(const float* __restrict__ pos) {
    __shared__ float sH[256], sX[256], sY[256];
    int t = threadIdx.x;
    sH[t] = g_partH[t]; sX[t] = g_partX[t]; sY[t] = g_partY[t];
    __syncthreads();
    for (int s = 128; s > 0; s >>= 1) {
        if (t < s) {
            sH[t] = fmaxf(sH[t], sH[t + s]);
            sX[t] = fminf(sX[t], sX[t + s]);
            sY[t] = fminf(sY[t], sY[t + s]);
        }
        __syncthreads();
    }
    float h  = sH[0];
    float qx = sX[0] - h;
    float qy = sY[0] - h;

    int i = blockIdx.x * blockDim.x + threadIdx.x;
    if (i >= NP) return;
    float2 p = ((const float2*)pos)[i];
    int ix = (int)ceilf((p.x - qx) / h);
    int iy = (int)ceilf((p.y - qy) / h);
    ix = min(max(ix, 0), GRIDW - 1);
    iy = min(max(iy, 0), GRIDW - 1);
    int lin = ix + GRIDW * iy;
    int slot = atomicAdd(&g_cellCount[lin], 1);
    if (slot < CAP)
        g_cellListP[lin * CAP + slot] = make_float4(__int_as_float(i), p.x, p.y, 0.0f);
}

// ------- kernel 3: warp-per-cell rank sort (gather-free) --------------------
__global__ void sortK() {
    int w = (blockIdx.x * blockDim.x + threadIdx.x) >> 5;
    if (w >= NUM_CELLS) return;
    int lane = threadIdx.x & 31;
    int cnt = g_cellCount[w];
    int m = min(cnt, KSLOT);
    float4 e = make_float4(0.f, 0.f, 0.f, 0.f);
    int idx = 0x7fffffff;
    if (lane < m) {
        e = g_cellListP[w * CAP + lane];
        idx = __float_as_int(e.x);
    }
    int rank = 0;
    for (int j = 0; j < m; j++) {
        int v = __shfl_sync(FULLM, idx, j);
        rank += (v < idx);
    }
    if (lane == 0) g_tabCnt[w] = m;
    if (lane < m) g_tab[w * KSLOT + rank] = e;
}

// ------- kernel 4: warp-per-cell neighbor search -----------------------------
__global__ void searchK(const float* __restrict__ sup,
                        float* __restrict__ out) {
    int w = (blockIdx.x * blockDim.x + threadIdx.x) >> 5;   // warp id = cell
    if (w >= NUM_CELLS) return;
    int lane = threadIdx.x & 31;

    // ---- stencil setup (once per cell) ----
    int c = NUM_CELLS, m = 0;
    if (lane < 9) {
        int dxo = lane / 3 - 1;
        int dyo = lane % 3 - 1;
        int cc = w + dxo + GRIDW * dyo;
        cc = min(max(cc, 0), NUM_CELLS);
        c = cc;
        m = g_tabCnt[cc];
    }
    int incl = m;
#pragma unroll
    for (int d = 1; d < 16; d <<= 1) {
        int v = __shfl_up_sync(FULLM, incl, d);
        if (lane >= d) incl += v;
    }
    int pref = incl - m;
    int T = __shfl_sync(FULLM, incl, 8);

    int qcnt = __shfl_sync(FULLM, m, 4);      // center cell = this cell's queries
    if (qcnt == 0) return;

    int p1 = __shfl_sync(FULLM, pref, 1);
    int p2 = __shfl_sync(FULLM, pref, 2);
    int p3 = __shfl_sync(FULLM, pref, 3);
    int p4 = __shfl_sync(FULLM, pref, 4);
    int p5 = __shfl_sync(FULLM, pref, 5);
    int p6 = __shfl_sync(FULLM, pref, 6);
    int p7 = __shfl_sync(FULLM, pref, 7);
    int p8 = __shfl_sync(FULLM, pref, 8);

    // ---- query data (direct load, known-correct R4 path) ----
    float4 qe = make_float4(0.f, 0.f, 0.f, 0.f);
    float hq = 0.0f;
    int qidl = 0;
    if (lane < qcnt) {
        qe = g_cellListP[w * CAP + lane];
        qidl = __float_as_int(qe.x);
        hq = __ldg(&sup[qidl]);               // parallel prefetch of supports
    }

    // ---- preload candidates (chunks 0,1 cover T <= 64) ----
    float4 e0 = make_float4(0.f, 0.f, 0.f, 0.f);
    float4 e1 = make_float4(0.f, 0.f, 0.f, 0.f);
    bool act0 = lane < T;
    {
        int t = lane;
        int o = (t >= p1) + (t >= p2) + (t >= p3) + (t >= p4) +
                (t >= p5) + (t >= p6) + (t >= p7) + (t >= p8);
        int cc = __shfl_sync(FULLM, c, o);
        int po = __shfl_sync(FULLM, pref, o);
        if (act0) e0 = g_tab[cc * KSLOT + (t - po)];
    }
    bool act1 = (lane + 32) < T;
    if (T > 32) {
        int t = lane + 32;
        int o = (t >= p1) + (t >= p2) + (t >= p3) + (t >= p4) +
                (t >= p5) + (t >= p6) + (t >= p7) + (t >= p8);
        int cc = __shfl_sync(FULLM, c, o);
        int po = __shfl_sync(FULLM, pref, o);
        if (act1) e1 = g_tab[cc * KSLOT + (t - po)];
    }
    float n0 = (float)__float_as_int(e0.x);
    float n1 = (float)__float_as_int(e1.x);

    float* outN = out;                              // (N, 64) neighbor indices
    float* outC = out + (size_t)NP * MAXN;          // (N,)    counts
    float* outR = outC + NP;                        // (N, 64) radial

    // ---- per-query loop ----
    for (int q = 0; q < qcnt; q++) {
        float px = __shfl_sync(FULLM, qe.y, q);
        float py = __shfl_sync(FULLM, qe.z, q);
        float h  = __shfl_sync(FULLM, hq, q);
        int  qid = __shfl_sync(FULLM, qidl, q);
        size_t base = (size_t)qid * MAXN;

        int cnt = 0;
        // chunk 0
        {
            float dx = __fsub_rn(e0.y, px);
            float dy = __fsub_rn(e0.z, py);
            float dist = __fsqrt_rn(__fadd_rn(__fmul_rn(dx, dx), __fmul_rn(dy, dy)));
            bool ok = act0 && (dist <= h);
            unsigned bal = __ballot_sync(FULLM, ok);
            int slot = __popc(bal & ((1u << lane) - 1u));
            if (ok && slot < MAXN) {
                __stcs(&outN[base + slot], n0);
                __stcs(&outR[base + slot], __fdiv_rn(dist, h));
            }
            cnt = __popc(bal);
        }
        // chunk 1
        if (T > 32) {
            float dx = __fsub_rn(e1.y, px);
            float dy = __fsub_rn(e1.z, py);
            float dist = __fsqrt_rn(__fadd_rn(__fmul_rn(dx, dx), __fmul_rn(dy, dy)));
            bool ok = act1 && (dist <= h);
            unsigned bal = __ballot_sync(FULLM, ok);
            int slot = cnt + __popc(bal & ((1u << lane) - 1u));
            if (ok && slot < MAXN) {
                __stcs(&outN[base + slot], n1);
                __stcs(&outR[base + slot], __fdiv_rn(dist, h));
            }
            cnt += __popc(bal);
        }
        // rare: T > 64
        for (int tb = 64; tb < T; tb += 32) {
            int t = tb + lane;
            bool act = t < T;
            int o = (t >= p1) + (t >= p2) + (t >= p3) + (t >= p4) +
                    (t >= p5) + (t >= p6) + (t >= p7) + (t >= p8);
            int cc = __shfl_sync(FULLM, c, o);
            int po = __shfl_sync(FULLM, pref, o);
            float nidx = 0.0f, dist = 0.0f;
            bool ok = false;
            if (act) {
                float4 e = g_tab[cc * KSLOT + (t - po)];
                float dx = __fsub_rn(e.y, px);
                float dy = __fsub_rn(e.z, py);
                dist = __fsqrt_rn(__fadd_rn(__fmul_rn(dx, dx), __fmul_rn(dy, dy)));
                nidx = (float)__float_as_int(e.x);
                ok = dist <= h;
            }
            unsigned bal = __ballot_sync(FULLM, ok);
            int slot = cnt + __popc(bal & ((1u << lane) - 1u));
            if (ok && slot < MAXN) {
                __stcs(&outN[base + slot], nidx);
                __stcs(&outR[base + slot], __fdiv_rn(dist, h));
            }
            cnt += __popc(bal);
        }
        // tail fill
        int start = min(cnt, MAXN);
        for (int k = start + lane; k < MAXN; k += 32) {
            __stcs(&outN[base + k], -1.0f);
            __stcs(&outR[base + k], 0.0f);
        }
        if (lane == 0) __stcs(&outC[qid], (float)cnt);
    }
}

// ---------------- launch ------------------------------------------------------
extern "C" void kernel_launch(void* const* d_in, const int* in_sizes, int n_in,
                              void* d_out, int out_size) {
    const float* pos = (const float*)d_in[0];   // (N, 2) float32
    const float* sup = (const float*)d_in[1];   // (N,)   float32
    float* out = (float*)d_out;

    initRedK<<<256, 256>>>(pos, sup);
    binK<<<NP / 256, 256>>>(pos);
    sortK<<<(NUM_CELLS * 32) / 256, 256>>>();
    searchK<<<(NUM_CELLS * 32) / 256, 256>>>(sup, out);
}

// round 7
// speedup vs baseline: 1.3940x; 1.1893x over previous
#include <cuda_runtime.h>

#define NP 262144
#define GRIDW 256
#define NUM_CELLS (GRIDW*GRIDW)
#define KSLOT 32
#define CAP 32
#define MAXN 64
#define FULLM 0xffffffffu

// ---------------- scratch (device globals) ----------------------------------
__device__ float    g_partH[256];
__device__ float    g_partX[256];
__device__ float    g_partY[256];
__device__ int      g_cellCount[NUM_CELLS + 1];
__device__ float4   g_cellListP[NUM_CELLS * CAP];       // {bits(idx), x, y, pad}
__device__ int      g_tabCnt[NUM_CELLS + 1];
__device__ float4   g_tab[(NUM_CELLS + 1) * KSLOT];     // {bits(idx), x, y, pad}

// ------- kernel 1: zero counts + per-block partial reductions ---------------
__global__ void initRedK(const float* __restrict__ pos, const float* __restrict__ sup) {
    int tid = blockIdx.x * blockDim.x + threadIdx.x;
    for (int c = tid; c <= NUM_CELLS; c += gridDim.x * blockDim.x)
        g_cellCount[c] = 0;
    if (tid == 0) g_tabCnt[NUM_CELLS] = 0;   // sentinel cell: always empty

    __shared__ float sH[256], sX[256], sY[256];
    float h = 0.0f, x = __int_as_float(0x7f800000), y = __int_as_float(0x7f800000);
    for (int i = tid; i < NP; i += gridDim.x * blockDim.x) {
        h = fmaxf(h, sup[i]);
        float2 p = ((const float2*)pos)[i];
        x = fminf(x, p.x);
        y = fminf(y, p.y);
    }
    int t = threadIdx.x;
    sH[t] = h; sX[t] = x; sY[t] = y;
    __syncthreads();
    for (int s = 128; s > 0; s >>= 1) {
        if (t < s) {
            sH[t] = fmaxf(sH[t], sH[t + s]);
            sX[t] = fminf(sX[t], sX[t + s]);
            sY[t] = fminf(sY[t], sY[t + s]);
        }
        __syncthreads();
    }
    if (t == 0) {
        g_partH[blockIdx.x] = sH[0];
        g_partX[blockIdx.x] = sX[0];
        g_partY[blockIdx.x] = sY[0];
    }
}

// ------- kernel 2: combine partials (prologue) + bin particles --------------
__global__ void binK(const float* __restrict__ pos) {
    __shared__ float sH[256], sX[256], sY[256];
    int t = threadIdx.x;
    sH[t] = g_partH[t]; sX[t] = g_partX[t]; sY[t] = g_partY[t];
    __syncthreads();
    for (int s = 128; s > 0; s >>= 1) {
        if (t < s) {
            sH[t] = fmaxf(sH[t], sH[t + s]);
            sX[t] = fminf(sX[t], sX[t + s]);
            sY[t] = fminf(sY[t], sY[t + s]);
        }
        __syncthreads();
    }
    float h  = sH[0];
    float qx = sX[0] - h;
    float qy = sY[0] - h;

    int i = blockIdx.x * blockDim.x + threadIdx.x;
    if (i >= NP) return;
    float2 p = ((const float2*)pos)[i];
    int ix = (int)ceilf((p.x - qx) / h);
    int iy = (int)ceilf((p.y - qy) / h);
    ix = min(max(ix, 0), GRIDW - 1);
    iy = min(max(iy, 0), GRIDW - 1);
    int lin = ix + GRIDW * iy;
    int slot = atomicAdd(&g_cellCount[lin], 1);
    if (slot < CAP)
        g_cellListP[lin * CAP + slot] = make_float4(__int_as_float(i), p.x, p.y, 0.0f);
}

// ------- kernel 3: warp-per-cell rank sort (gather-free) --------------------
__global__ void sortK() {
    int w = (blockIdx.x * blockDim.x + threadIdx.x) >> 5;
    if (w >= NUM_CELLS) return;
    int lane = threadIdx.x & 31;
    int cnt = g_cellCount[w];
    int m = min(cnt, KSLOT);
    float4 e = make_float4(0.f, 0.f, 0.f, 0.f);
    int idx = 0x7fffffff;
    if (lane < m) {
        e = g_cellListP[w * CAP + lane];
        idx = __float_as_int(e.x);
    }
    int rank = 0;
    for (int j = 0; j < m; j++) {
        int v = __shfl_sync(FULLM, idx, j);
        rank += (v < idx);
    }
    if (lane == 0) g_tabCnt[w] = m;
    if (lane < m) g_tab[w * KSLOT + rank] = e;
}

// ------- kernel 4: warp-per-cell neighbor search -----------------------------
__global__ void searchK(const float* __restrict__ sup,
                        float* __restrict__ out) {
    int w = (blockIdx.x * blockDim.x + threadIdx.x) >> 5;   // warp id = cell
    if (w >= NUM_CELLS) return;
    int lane = threadIdx.x & 31;

    // ---- stencil setup (once per cell) ----
    int c = NUM_CELLS, m = 0;
    if (lane < 9) {
        int dxo = lane / 3 - 1;
        int dyo = lane % 3 - 1;
        int cc = w + dxo + GRIDW * dyo;
        cc = min(max(cc, 0), NUM_CELLS);
        c = cc;
        m = g_tabCnt[cc];
    }
    int incl = m;
#pragma unroll
    for (int d = 1; d < 16; d <<= 1) {
        int v = __shfl_up_sync(FULLM, incl, d);
        if (lane >= d) incl += v;
    }
    int pref = incl - m;
    int T = __shfl_sync(FULLM, incl, 8);

    int qcnt = __shfl_sync(FULLM, m, 4);      // center cell = this cell's queries
    if (qcnt == 0) return;

    int p1 = __shfl_sync(FULLM, pref, 1);
    int p2 = __shfl_sync(FULLM, pref, 2);
    int p3 = __shfl_sync(FULLM, pref, 3);
    int p4 = __shfl_sync(FULLM, pref, 4);
    int p5 = __shfl_sync(FULLM, pref, 5);
    int p6 = __shfl_sync(FULLM, pref, 6);
    int p7 = __shfl_sync(FULLM, pref, 7);
    int p8 = __shfl_sync(FULLM, pref, 8);

    // ---- query data (direct load) ----
    float4 qe = make_float4(0.f, 0.f, 0.f, 0.f);
    float hq = 0.0f;
    int qidl = 0;
    if (lane < qcnt) {
        qe = g_cellListP[w * CAP + lane];
        qidl = __float_as_int(qe.x);
        hq = __ldg(&sup[qidl]);               // parallel prefetch of supports
    }

    // ---- preload candidates (chunks 0,1 cover T <= 64) ----
    float4 e0 = make_float4(0.f, 0.f, 0.f, 0.f);
    float4 e1 = make_float4(0.f, 0.f, 0.f, 0.f);
    bool act0 = lane < T;
    {
        int t = lane;
        int o = (t >= p1) + (t >= p2) + (t >= p3) + (t >= p4) +
                (t >= p5) + (t >= p6) + (t >= p7) + (t >= p8);
        int cc = __shfl_sync(FULLM, c, o);
        int po = __shfl_sync(FULLM, pref, o);
        if (act0) e0 = g_tab[cc * KSLOT + (t - po)];
    }
    bool act1 = (lane + 32) < T;
    if (T > 32) {
        int t = lane + 32;
        int o = (t >= p1) + (t >= p2) + (t >= p3) + (t >= p4) +
                (t >= p5) + (t >= p6) + (t >= p7) + (t >= p8);
        int cc = __shfl_sync(FULLM, c, o);
        int po = __shfl_sync(FULLM, pref, o);
        if (act1) e1 = g_tab[cc * KSLOT + (t - po)];
    }
    float n0 = (float)__float_as_int(e0.x);
    float n1 = (float)__float_as_int(e1.x);

    float* outN = out;                              // (N, 64) neighbor indices
    float* outC = out + (size_t)NP * MAXN;          // (N,)    counts
    float* outR = outC + NP;                        // (N, 64) radial

    int myCnt = 0;                                  // this lane's query count

    // ---- per-query loop ----
    for (int q = 0; q < qcnt; q++) {
        float px = __shfl_sync(FULLM, qe.y, q);
        float py = __shfl_sync(FULLM, qe.z, q);
        float h  = __shfl_sync(FULLM, hq, q);
        int  qid = __shfl_sync(FULLM, qidl, q);
        float rh = __frcp_rn(h);                    // 1 MUFU replaces 2 fdiv
        size_t base = (size_t)qid * MAXN;

        int cnt;
        // chunk 0
        {
            float dx = __fsub_rn(e0.y, px);
            float dy = __fsub_rn(e0.z, py);
            float dist = __fsqrt_rn(__fadd_rn(__fmul_rn(dx, dx), __fmul_rn(dy, dy)));
            bool ok = act0 && (dist <= h);
            unsigned bal = __ballot_sync(FULLM, ok);
            int slot = __popc(bal & ((1u << lane) - 1u));
            if (ok) {                                // slot <= 31 < MAXN always
                __stcs(&outN[base + slot], n0);
                __stcs(&outR[base + slot], __fmul_rn(dist, rh));
            }
            cnt = __popc(bal);
        }
        // chunk 1
        if (T > 32) {
            float dx = __fsub_rn(e1.y, px);
            float dy = __fsub_rn(e1.z, py);
            float dist = __fsqrt_rn(__fadd_rn(__fmul_rn(dx, dx), __fmul_rn(dy, dy)));
            bool ok = act1 && (dist <= h);
            unsigned bal = __ballot_sync(FULLM, ok);
            int slot = cnt + __popc(bal & ((1u << lane) - 1u));
            if (ok) {                                // slot <= 63 < MAXN always
                __stcs(&outN[base + slot], n1);
                __stcs(&outR[base + slot], __fmul_rn(dist, rh));
            }
            cnt += __popc(bal);
        }
        // rare: T > 64
        for (int tb = 64; tb < T; tb += 32) {
            int t = tb + lane;
            bool act = t < T;
            int o = (t >= p1) + (t >= p2) + (t >= p3) + (t >= p4) +
                    (t >= p5) + (t >= p6) + (t >= p7) + (t >= p8);
            int cc = __shfl_sync(FULLM, c, o);
            int po = __shfl_sync(FULLM, pref, o);
            float nidx = 0.0f, dist = 0.0f;
            bool ok = false;
            if (act) {
                float4 e = g_tab[cc * KSLOT + (t - po)];
                float dx = __fsub_rn(e.y, px);
                float dy = __fsub_rn(e.z, py);
                dist = __fsqrt_rn(__fadd_rn(__fmul_rn(dx, dx), __fmul_rn(dy, dy)));
                nidx = (float)__float_as_int(e.x);
                ok = dist <= h;
            }
            unsigned bal = __ballot_sync(FULLM, ok);
            int slot = cnt + __popc(bal & ((1u << lane) - 1u));
            if (ok && slot < MAXN) {
                __stcs(&outN[base + slot], nidx);
                __stcs(&outR[base + slot], __fmul_rn(dist, rh));
            }
            cnt += __popc(bal);
        }
        // tail fill: unrolled two predicated steps (tail length <= 64)
        int start = min(cnt, MAXN);
        int k0 = start + lane;
        if (k0 < MAXN) {
            __stcs(&outN[base + k0], -1.0f);
            __stcs(&outR[base + k0], 0.0f);
        }
        int k1 = k0 + 32;
        if (k1 < MAXN) {
            __stcs(&outN[base + k1], -1.0f);
            __stcs(&outR[base + k1], 0.0f);
        }
        if (q == lane) myCnt = cnt;                 // defer count store
    }
    if (lane < qcnt) __stcs(&outC[qidl], (float)myCnt);
}

// ---------------- launch ------------------------------------------------------
extern "C" void kernel_launch(void* const* d_in, const int* in_sizes, int n_in,
                              void* d_out, int out_size) {
    const float* pos = (const float*)d_in[0];   // (N, 2) float32
    const float* sup = (const float*)d_in[1];   // (N,)   float32
    float* out = (float*)d_out;

    initRedK<<<256, 256>>>(pos, sup);
    binK<<<NP / 256, 256>>>(pos);
    sortK<<<(NUM_CELLS * 32) / 256, 256>>>();
    searchK<<<(NUM_CELLS * 32) / 256, 256>>>(sup, out);
}

// round 8
// speedup vs baseline: 1.7182x; 1.2325x over previous
#include <cuda_runtime.h>

#define NP 262144
#define GRIDW 256
#define NUM_CELLS (GRIDW*GRIDW)
#define KSLOT 32
#define CAP 32
#define MAXN 64
#define FULLM 0xffffffffu

// ---------------- scratch (device globals) ----------------------------------
__device__ float    g_partH[256];
__device__ float    g_partX[256];
__device__ float    g_partY[256];
__device__ int      g_cellCount[NUM_CELLS + 1];
__device__ float4   g_cellListP[NUM_CELLS * CAP];       // {bits(idx), x, y, pad}
__device__ int      g_tabCnt[NUM_CELLS + 1];
__device__ float4   g_tab[(NUM_CELLS + 1) * KSLOT];     // {bits(idx), x, y, pad}
__device__ float2   g_aux[NP];                          // {t = d2 threshold, rh = 1/h}

// ------- kernel 1: zero counts + per-block partial reductions ---------------
__global__ void initRedK(const float* __restrict__ pos, const float* __restrict__ sup) {
    int tid = blockIdx.x * blockDim.x + threadIdx.x;
    for (int c = tid; c <= NUM_CELLS; c += gridDim.x * blockDim.x)
        g_cellCount[c] = 0;
    if (tid == 0) g_tabCnt[NUM_CELLS] = 0;   // sentinel cell: always empty

    __shared__ float sH[256], sX[256], sY[256];
    float h = 0.0f, x = __int_as_float(0x7f800000), y = __int_as_float(0x7f800000);
    for (int i = tid; i < NP; i += gridDim.x * blockDim.x) {
        h = fmaxf(h, sup[i]);
        float2 p = ((const float2*)pos)[i];
        x = fminf(x, p.x);
        y = fminf(y, p.y);
    }
    int t = threadIdx.x;
    sH[t] = h; sX[t] = x; sY[t] = y;
    __syncthreads();
    for (int s = 128; s > 0; s >>= 1) {
        if (t < s) {
            sH[t] = fmaxf(sH[t], sH[t + s]);
            sX[t] = fminf(sX[t], sX[t + s]);
            sY[t] = fminf(sY[t], sY[t + s]);
        }
        __syncthreads();
    }
    if (t == 0) {
        g_partH[blockIdx.x] = sH[0];
        g_partX[blockIdx.x] = sX[0];
        g_partY[blockIdx.x] = sY[0];
    }
}

// ------- kernel 2: combine partials + bin particles + per-particle aux ------
__global__ void binK(const float* __restrict__ pos, const float* __restrict__ sup) {
    __shared__ float sH[256], sX[256], sY[256];
    int t = threadIdx.x;
    sH[t] = g_partH[t]; sX[t] = g_partX[t]; sY[t] = g_partY[t];
    __syncthreads();
    for (int s = 128; s > 0; s >>= 1) {
        if (t < s) {
            sH[t] = fmaxf(sH[t], sH[t + s]);
            sX[t] = fminf(sX[t], sX[t + s]);
            sY[t] = fminf(sY[t], sY[t + s]);
        }
        __syncthreads();
    }
    float hM = sH[0];
    float qx = sX[0] - hM;
    float qy = sY[0] - hM;

    int i = blockIdx.x * blockDim.x + threadIdx.x;
    if (i >= NP) return;
    float2 p = ((const float2*)pos)[i];
    int ix = (int)ceilf((p.x - qx) / hM);
    int iy = (int)ceilf((p.y - qy) / hM);
    ix = min(max(ix, 0), GRIDW - 1);
    iy = min(max(iy, 0), GRIDW - 1);
    int lin = ix + GRIDW * iy;
    int slot = atomicAdd(&g_cellCount[lin], 1);
    if (slot < CAP)
        g_cellListP[lin * CAP + slot] = make_float4(__int_as_float(i), p.x, p.y, 0.0f);

    // ---- per-particle: t = largest float with fl(sqrt(t)) <= h  (exact) ----
    float h = sup[i];
    float u = __fmul_rn(h, h);
    // step down (<= 3 ulps needed)
    if (__fsqrt_rn(u) > h) u = __int_as_float(__float_as_int(u) - 1);
    if (__fsqrt_rn(u) > h) u = __int_as_float(__float_as_int(u) - 1);
    if (__fsqrt_rn(u) > h) u = __int_as_float(__float_as_int(u) - 1);
    // step up while next float still satisfies (<= 3 ulps)
    float un = __int_as_float(__float_as_int(u) + 1);
    if (__fsqrt_rn(un) <= h) {
        u = un; un = __int_as_float(__float_as_int(u) + 1);
        if (__fsqrt_rn(un) <= h) {
            u = un; un = __int_as_float(__float_as_int(u) + 1);
            if (__fsqrt_rn(un) <= h) u = un;
        }
    }
    g_aux[i] = make_float2(u, __frcp_rn(h));
}

// ------- kernel 3: warp-per-cell rank sort (gather-free) --------------------
__global__ void sortK() {
    int w = (blockIdx.x * blockDim.x + threadIdx.x) >> 5;
    if (w >= NUM_CELLS) return;
    int lane = threadIdx.x & 31;
    int cnt = g_cellCount[w];
    int m = min(cnt, KSLOT);
    float4 e = make_float4(0.f, 0.f, 0.f, 0.f);
    int idx = 0x7fffffff;
    if (lane < m) {
        e = g_cellListP[w * CAP + lane];
        idx = __float_as_int(e.x);
    }
    int rank = 0;
    for (int j = 0; j < m; j++) {
        int v = __shfl_sync(FULLM, idx, j);
        rank += (v < idx);
    }
    if (lane == 0) g_tabCnt[w] = m;
    if (lane < m) g_tab[w * KSLOT + rank] = e;
}

__device__ __forceinline__ float sqrt_approx(float x) {
    float r;
    asm("sqrt.approx.f32 %0, %1;" : "=f"(r) : "f"(x));
    return r;
}

// ------- kernel 4: warp-per-cell neighbor search -----------------------------
__global__ void searchK(float* __restrict__ out) {
    int w = (blockIdx.x * blockDim.x + threadIdx.x) >> 5;   // warp id = cell
    if (w >= NUM_CELLS) return;
    int lane = threadIdx.x & 31;

    // ---- stencil setup (once per cell) ----
    int c = NUM_CELLS, m = 0;
    if (lane < 9) {
        int dxo = lane / 3 - 1;
        int dyo = lane % 3 - 1;
        int cc = w + dxo + GRIDW * dyo;
        cc = min(max(cc, 0), NUM_CELLS);
        c = cc;
        m = g_tabCnt[cc];
    }
    int incl = m;
#pragma unroll
    for (int d = 1; d < 16; d <<= 1) {
        int v = __shfl_up_sync(FULLM, incl, d);
        if (lane >= d) incl += v;
    }
    int pref = incl - m;
    int T = __shfl_sync(FULLM, incl, 8);

    int qcnt = __shfl_sync(FULLM, m, 4);      // center cell = this cell's queries
    if (qcnt == 0) return;

    int p1 = __shfl_sync(FULLM, pref, 1);
    int p2 = __shfl_sync(FULLM, pref, 2);
    int p3 = __shfl_sync(FULLM, pref, 3);
    int p4 = __shfl_sync(FULLM, pref, 4);
    int p5 = __shfl_sync(FULLM, pref, 5);
    int p6 = __shfl_sync(FULLM, pref, 6);
    int p7 = __shfl_sync(FULLM, pref, 7);
    int p8 = __shfl_sync(FULLM, pref, 8);

    // ---- query data (direct load) ----
    float4 qe = make_float4(0.f, 0.f, 0.f, 0.f);
    float tL = 0.0f, rhL = 0.0f;
    int qidl = 0;
    if (lane < qcnt) {
        qe = g_cellListP[w * CAP + lane];
        qidl = __float_as_int(qe.x);
        float2 aux = __ldg(&g_aux[qidl]);     // parallel prefetch {t, 1/h}
        tL = aux.x; rhL = aux.y;
    }

    // ---- preload candidates (chunks 0,1 cover T <= 64) ----
    float4 e0 = make_float4(0.f, 0.f, 0.f, 0.f);
    float4 e1 = make_float4(0.f, 0.f, 0.f, 0.f);
    bool act0 = lane < T;
    {
        int t = lane;
        int o = (t >= p1) + (t >= p2) + (t >= p3) + (t >= p4) +
                (t >= p5) + (t >= p6) + (t >= p7) + (t >= p8);
        int cc = __shfl_sync(FULLM, c, o);
        int po = __shfl_sync(FULLM, pref, o);
        if (act0) e0 = g_tab[cc * KSLOT + (t - po)];
    }
    bool act1 = (lane + 32) < T;
    if (T > 32) {
        int t = lane + 32;
        int o = (t >= p1) + (t >= p2) + (t >= p3) + (t >= p4) +
                (t >= p5) + (t >= p6) + (t >= p7) + (t >= p8);
        int cc = __shfl_sync(FULLM, c, o);
        int po = __shfl_sync(FULLM, pref, o);
        if (act1) e1 = g_tab[cc * KSLOT + (t - po)];
    }
    float n0 = (float)__float_as_int(e0.x);
    float n1 = (float)__float_as_int(e1.x);

    float* outN = out;                              // (N, 64) neighbor indices
    float* outC = out + (size_t)NP * MAXN;          // (N,)    counts
    float* outR = outC + NP;                        // (N, 64) radial

    int myCnt = 0;                                  // this lane's query count

    // ---- per-query loop ----
    for (int q = 0; q < qcnt; q++) {
        float px = __shfl_sync(FULLM, qe.y, q);
        float py = __shfl_sync(FULLM, qe.z, q);
        float tq = __shfl_sync(FULLM, tL, q);
        float rh = __shfl_sync(FULLM, rhL, q);
        int  qid = __shfl_sync(FULLM, qidl, q);
        int  rbase = qid << 6;                      // 32-bit row offset
        float* pN = outN + rbase;
        float* pR = outR + rbase;

        int cnt;
        // chunk 0
        {
            float dx = __fsub_rn(e0.y, px);
            float dy = __fsub_rn(e0.z, py);
            float d2 = __fadd_rn(__fmul_rn(dx, dx), __fmul_rn(dy, dy));
            bool ok = act0 && (d2 <= tq);           // exact selection via threshold
            unsigned bal = __ballot_sync(FULLM, ok);
            int slot = __popc(bal & ((1u << lane) - 1u));
            if (ok) {
                __stcs(&pN[slot], n0);
                __stcs(&pR[slot], __fmul_rn(sqrt_approx(d2), rh));
            }
            cnt = __popc(bal);
        }
        // chunk 1
        if (T > 32) {
            float dx = __fsub_rn(e1.y, px);
            float dy = __fsub_rn(e1.z, py);
            float d2 = __fadd_rn(__fmul_rn(dx, dx), __fmul_rn(dy, dy));
            bool ok = act1 && (d2 <= tq);
            unsigned bal = __ballot_sync(FULLM, ok);
            int slot = cnt + __popc(bal & ((1u << lane) - 1u));
            if (ok) {
                __stcs(&pN[slot], n1);
                __stcs(&pR[slot], __fmul_rn(sqrt_approx(d2), rh));
            }
            cnt += __popc(bal);
        }
        // rare: T > 64
        for (int tb = 64; tb < T; tb += 32) {
            int t = tb + lane;
            bool act = t < T;
            int o = (t >= p1) + (t >= p2) + (t >= p3) + (t >= p4) +
                    (t >= p5) + (t >= p6) + (t >= p7) + (t >= p8);
            int cc = __shfl_sync(FULLM, c, o);
            int po = __shfl_sync(FULLM, pref, o);
            float nidx = 0.0f, d2 = 0.0f;
            bool ok = false;
            if (act) {
                float4 e = g_tab[cc * KSLOT + (t - po)];
                float dx = __fsub_rn(e.y, px);
                float dy = __fsub_rn(e.z, py);
                d2 = __fadd_rn(__fmul_rn(dx, dx), __fmul_rn(dy, dy));
                nidx = (float)__float_as_int(e.x);
                ok = d2 <= tq;
            }
            unsigned bal = __ballot_sync(FULLM, ok);
            int slot = cnt + __popc(bal & ((1u << lane) - 1u));
            if (ok && slot < MAXN) {
                __stcs(&pN[slot], nidx);
                __stcs(&pR[slot], __fmul_rn(sqrt_approx(d2), rh));
            }
            cnt += __popc(bal);
        }
        // tail fill: unrolled two predicated steps (tail length <= 64)
        int start = min(cnt, MAXN);
        int k0 = start + lane;
        if (k0 < MAXN) {
            __stcs(&pN[k0], -1.0f);
            __stcs(&pR[k0], 0.0f);
        }
        int k1 = k0 + 32;
        if (k1 < MAXN) {
            __stcs(&pN[k1], -1.0f);
            __stcs(&pR[k1], 0.0f);
        }
        if (q == lane) myCnt = cnt;                 // defer count store
    }
    if (lane < qcnt) __stcs(&outC[qidl], (float)myCnt);
}

// ---------------- launch ------------------------------------------------------
extern "C" void kernel_launch(void* const* d_in, const int* in_sizes, int n_in,
                              void* d_out, int out_size) {
    const float* pos = (const float*)d_in[0];   // (N, 2) float32
    const float* sup = (const float*)d_in[1];   // (N,)   float32
    float* out = (float*)d_out;

    initRedK<<<256, 256>>>(pos, sup);
    binK<<<NP / 256, 256>>>(pos, sup);
    sortK<<<(NUM_CELLS * 32) / 256, 256>>>();
    searchK<<<(NUM_CELLS * 32) / 256, 256>>>(out);
}